// round 3
// baseline (speedup 1.0000x reference)
#include <cuda_runtime.h>

#define BB 32
#define NN 128
#define HH 100
#define ROWS (BB*NN)   // 4096

// Scratch (static device allocations — allowed)
__device__ float g_hidden[ROWS*HH];
__device__ float g_hv[ROWS*HH];
__device__ float g_hw[ROWS*HH];
__device__ float g_msg[ROWS*HH];
__device__ float g_gterm[ROWS*HH];
__device__ int   g_nodemask[ROWS];

// ---- packed f32x2 helpers (sm_100+; ptxas never auto-fuses these) ----------
__device__ __forceinline__ unsigned long long fma2(unsigned long long a,
                                                   unsigned long long b,
                                                   unsigned long long c) {
    unsigned long long d;
    asm("fma.rn.f32x2 %0, %1, %2, %3;" : "=l"(d) : "l"(a), "l"(b), "l"(c));
    return d;
}
__device__ __forceinline__ unsigned long long pack2(float w) {
    unsigned long long d;
    asm("mov.b64 %0, {%1, %1};" : "=l"(d) : "f"(w));
    return d;
}
__device__ __forceinline__ void unpack2(unsigned long long v, float& lo, float& hi) {
    asm("mov.b64 {%0, %1}, %2;" : "=f"(lo), "=f"(hi) : "l"(v));
}

// ---------------------------------------------------------------------------
// init: hidden = nodes; node_mask[row] = (sum_w sum_e edges[row,w,e]) != 0
// ---------------------------------------------------------------------------
__global__ void k_init(const float* __restrict__ nodes,
                       const float* __restrict__ edges) {
    int row = blockIdx.x;
    int tid = threadIdx.x;
    if (tid < HH) g_hidden[row*HH + tid] = nodes[row*HH + tid];

    const float4* e4 = (const float4*)edges + (size_t)row * NN;
    float4 e = e4[tid];
    float s = (e.x + e.y) + (e.z + e.w);
    __shared__ float red[128];
    red[tid] = s;
    __syncthreads();
    for (int off = 64; off > 0; off >>= 1) {
        if (tid < off) red[tid] += red[tid + off];
        __syncthreads();
    }
    if (tid == 0) g_nodemask[row] = (red[0] != 0.0f) ? 1 : 0;
}

// ---------------------------------------------------------------------------
// proj: hv = hidden @ Wv, hw = hidden @ Ww.
// 8 rows/block, grid=512. Wv+Ww staged in shared (80KB); x staged transposed
// as (k, r0..r7). Inner loop: 2 LDS.128 + 2 LDS.32 + 2 pack + 8 FMA2.
// dyn smem = 80000 + 3200 = 83200 B.
// ---------------------------------------------------------------------------
__global__ void k_proj(const float* __restrict__ Wv,
                       const float* __restrict__ Ww) {
    extern __shared__ float smem[];
    float* sW  = smem;            // [0,10000) = Wv, [10000,20000) = Ww
    float* sTf = smem + 20000;    // 8*HH floats, layout (k,r): sTf[k*8+r]

    int base = blockIdx.x * 8;
    int tid  = threadIdx.x;

    {   // stage weights as float4 (both matrices 10000 floats each)
        const float4* wv4 = (const float4*)Wv;
        const float4* ww4 = (const float4*)Ww;
        float4* s4 = (float4*)sW;
        for (int i = tid; i < 2500; i += 128) {
            s4[i]        = wv4[i];
            s4[2500 + i] = ww4[i];
        }
    }
    for (int i = tid; i < 8*HH; i += 128) {
        int r = i / HH, k = i - r*HH;
        sTf[k*8 + r] = g_hidden[(base + r)*HH + k];
    }
    __syncthreads();

    if (tid < HH) {
        int h = tid;
        const ulonglong2* sT2 = (const ulonglong2*)sTf;
        unsigned long long av0=0, av1=0, av2=0, av3=0;
        unsigned long long aw0=0, aw1=0, aw2=0, aw3=0;
        #pragma unroll 4
        for (int k = 0; k < HH; k++) {
            ulonglong2 a = sT2[2*k];       // rows 0-1, 2-3
            ulonglong2 b = sT2[2*k + 1];   // rows 4-5, 6-7
            unsigned long long wv = pack2(sW[k*HH + h]);
            unsigned long long ww = pack2(sW[10000 + k*HH + h]);
            av0 = fma2(a.x, wv, av0); av1 = fma2(a.y, wv, av1);
            av2 = fma2(b.x, wv, av2); av3 = fma2(b.y, wv, av3);
            aw0 = fma2(a.x, ww, aw0); aw1 = fma2(a.y, ww, aw1);
            aw2 = fma2(b.x, ww, aw2); aw3 = fma2(b.y, ww, aw3);
        }
        float rv[8], rw[8];
        unpack2(av0, rv[0], rv[1]); unpack2(av1, rv[2], rv[3]);
        unpack2(av2, rv[4], rv[5]); unpack2(av3, rv[6], rv[7]);
        unpack2(aw0, rw[0], rw[1]); unpack2(aw1, rw[2], rw[3]);
        unpack2(aw2, rw[4], rw[5]); unpack2(aw3, rw[6], rw[7]);
        #pragma unroll
        for (int r = 0; r < 8; r++) {
            g_hv[(base + r)*HH + h] = rv[r];
            g_hw[(base + r)*HH + h] = rw[r];
        }
    }
}

// ---------------------------------------------------------------------------
// msg: messages[b,v,h] = sum_w [adj!=0] * relu(hv[v,h] + hw[w,h] + e.We)
// mask pre-converted to {0.0,1.0} -> masked relu = FMNMX + FFMA.
// dual accumulators break the serial FADD chain.
// ---------------------------------------------------------------------------
__global__ void k_msg(const float* __restrict__ edges,
                      const float* __restrict__ We) {
    extern __shared__ float smem[];
    float*  s_hw  = smem;                        // 12800 floats
    float4* s_e   = (float4*)(smem + 12800);     // 512 float4
    float*  s_adj = smem + 12800 + 2048;         // 512 floats (0/1 mask)

    int bx  = blockIdx.x;
    int b   = bx >> 5;
    int v0  = (bx & 31) * 4;
    int tid = threadIdx.x;

    for (int i = tid; i < NN*HH; i += 512)
        s_hw[i] = g_hw[(b*NN)*HH + i];
    {
        int vloc = tid >> 7, w = tid & 127;
        const float4* e4 = (const float4*)edges;
        float4 e = e4[(size_t)((b*NN + v0 + vloc) * NN) + w];
        s_e[tid]   = e;
        float s = (e.x + e.y) + (e.z + e.w);
        s_adj[tid] = (s != 0.0f) ? 1.0f : 0.0f;
    }
    __syncthreads();

    int vloc = tid >> 7;
    int h    = tid & 127;
    if (h < HH) {
        float we0 = We[h], we1 = We[HH + h], we2 = We[2*HH + h], we3 = We[3*HH + h];
        float hvh = g_hv[(b*NN + v0 + vloc)*HH + h];
        const float4* ev = s_e   + (vloc << 7);
        const float*  av = s_adj + (vloc << 7);
        float acc0 = 0.f, acc1 = 0.f;
        #pragma unroll 4
        for (int w = 0; w < NN; w += 2) {
            float4 e0  = ev[w];
            float pre0 = hvh + s_hw[w*HH + h];
            pre0 = fmaf(e0.x, we0, pre0);
            pre0 = fmaf(e0.y, we1, pre0);
            pre0 = fmaf(e0.z, we2, pre0);
            pre0 = fmaf(e0.w, we3, pre0);
            acc0 = fmaf(fmaxf(pre0, 0.f), av[w], acc0);

            float4 e1  = ev[w + 1];
            float pre1 = hvh + s_hw[(w + 1)*HH + h];
            pre1 = fmaf(e1.x, we0, pre1);
            pre1 = fmaf(e1.y, we1, pre1);
            pre1 = fmaf(e1.z, we2, pre1);
            pre1 = fmaf(e1.w, we3, pre1);
            acc1 = fmaf(fmaxf(pre1, 0.f), av[w + 1], acc1);
        }
        g_msg[(b*NN + v0 + vloc)*HH + h] = acc0 + acc1;
    }
}

// ---------------------------------------------------------------------------
// update: hidden = node_mask ? tanh([hidden, msg] @ Wu) : hidden
// 8 rows/block, Wu (200x100, 80KB) staged in shared, f32x2 inner loop.
// dyn smem = 80000 + 6400 = 86400 B.
// ---------------------------------------------------------------------------
__global__ void k_update(const float* __restrict__ Wu) {
    extern __shared__ float smem[];
    float* sW  = smem;            // 20000 floats
    float* sTf = smem + 20000;    // (k in [0,200)) x (r in [0,8))

    int base = blockIdx.x * 8;
    int tid  = threadIdx.x;

    {
        const float4* w4 = (const float4*)Wu;
        float4* s4 = (float4*)sW;
        for (int i = tid; i < 5000; i += 128) s4[i] = w4[i];
    }
    for (int i = tid; i < 8*HH; i += 128) {
        int r = i / HH, k = i - r*HH;
        sTf[k*8 + r]          = g_hidden[(base + r)*HH + k];
        sTf[(HH + k)*8 + r]   = g_msg   [(base + r)*HH + k];
    }
    __syncthreads();

    if (tid < HH) {
        int h = tid;
        const ulonglong2* sT2 = (const ulonglong2*)sTf;
        unsigned long long a0=0, a1=0, a2=0, a3=0;
        #pragma unroll 4
        for (int k = 0; k < 2*HH; k++) {
            ulonglong2 a = sT2[2*k];
            ulonglong2 b = sT2[2*k + 1];
            unsigned long long w = pack2(sW[k*HH + h]);
            a0 = fma2(a.x, w, a0); a1 = fma2(a.y, w, a1);
            a2 = fma2(b.x, w, a2); a3 = fma2(b.y, w, a3);
        }
        float res[8];
        unpack2(a0, res[0], res[1]); unpack2(a1, res[2], res[3]);
        unpack2(a2, res[4], res[5]); unpack2(a3, res[6], res[7]);
        #pragma unroll
        for (int r = 0; r < 8; r++) {
            float oldv = sTf[h*8 + r];
            g_hidden[(base + r)*HH + h] =
                g_nodemask[base + r] ? tanhf(res[r]) : oldv;
        }
    }
}

// ---------------------------------------------------------------------------
// readout terms: gterm = node_mask ? relu([hidden, nodes] @ Wr) : 0
// same structure as k_update.
// ---------------------------------------------------------------------------
__global__ void k_readout(const float* __restrict__ nodes,
                          const float* __restrict__ Wr) {
    extern __shared__ float smem[];
    float* sW  = smem;
    float* sTf = smem + 20000;

    int base = blockIdx.x * 8;
    int tid  = threadIdx.x;

    {
        const float4* w4 = (const float4*)Wr;
        float4* s4 = (float4*)sW;
        for (int i = tid; i < 5000; i += 128) s4[i] = w4[i];
    }
    for (int i = tid; i < 8*HH; i += 128) {
        int r = i / HH, k = i - r*HH;
        sTf[k*8 + r]        = g_hidden[(base + r)*HH + k];
        sTf[(HH + k)*8 + r] = nodes   [(base + r)*HH + k];
    }
    __syncthreads();

    if (tid < HH) {
        int h = tid;
        const ulonglong2* sT2 = (const ulonglong2*)sTf;
        unsigned long long a0=0, a1=0, a2=0, a3=0;
        #pragma unroll 4
        for (int k = 0; k < 2*HH; k++) {
            ulonglong2 a = sT2[2*k];
            ulonglong2 b = sT2[2*k + 1];
            unsigned long long w = pack2(sW[k*HH + h]);
            a0 = fma2(a.x, w, a0); a1 = fma2(a.y, w, a1);
            a2 = fma2(b.x, w, a2); a3 = fma2(b.y, w, a3);
        }
        float res[8];
        unpack2(a0, res[0], res[1]); unpack2(a1, res[2], res[3]);
        unpack2(a2, res[4], res[5]); unpack2(a3, res[6], res[7]);
        #pragma unroll
        for (int r = 0; r < 8; r++) {
            float g = fmaxf(res[r], 0.f);
            g_gterm[(base + r)*HH + h] = g_nodemask[base + r] ? g : 0.f;
        }
    }
}

// ---------------------------------------------------------------------------
// reduce: out[b,h] = sum_v gterm[b,v,h]  (deterministic, no atomics)
// ---------------------------------------------------------------------------
__global__ void k_reduce(float* __restrict__ out) {
    int b   = blockIdx.x;
    int tid = threadIdx.x;           // 512
    int q   = tid >> 7;
    int h   = tid & 127;
    __shared__ float red[4][128];
    float acc = 0.f;
    if (h < HH) {
        int v0 = q * 32;
        #pragma unroll 4
        for (int v = v0; v < v0 + 32; v++)
            acc += g_gterm[(b*NN + v)*HH + h];
    }
    red[q][h] = acc;
    __syncthreads();
    if (q == 0 && h < HH)
        out[b*HH + h] = (red[0][h] + red[1][h]) + (red[2][h] + red[3][h]);
}

extern "C" void kernel_launch(void* const* d_in, const int* in_sizes, int n_in,
                              void* d_out, int out_size) {
    const float* nodes = (const float*)d_in[0];
    const float* edges = (const float*)d_in[1];
    const float* Wv    = (const float*)d_in[2];
    const float* Ww    = (const float*)d_in[3];
    const float* We    = (const float*)d_in[4];
    const float* Wu    = (const float*)d_in[5];
    const float* Wr    = (const float*)d_in[6];
    float* out = (float*)d_out;

    cudaFuncSetAttribute(k_msg,     cudaFuncAttributeMaxDynamicSharedMemorySize, 61440);
    cudaFuncSetAttribute(k_proj,    cudaFuncAttributeMaxDynamicSharedMemorySize, 83200);
    cudaFuncSetAttribute(k_update,  cudaFuncAttributeMaxDynamicSharedMemorySize, 86400);
    cudaFuncSetAttribute(k_readout, cudaFuncAttributeMaxDynamicSharedMemorySize, 86400);

    k_init<<<ROWS, 128>>>(nodes, edges);
    for (int p = 0; p < 3; p++) {
        k_proj<<<ROWS/8, 128, 83200>>>(Wv, Ww);
        k_msg<<<1024, 512, 61440>>>(edges, We);
        k_update<<<ROWS/8, 128, 86400>>>(Wu);
    }
    k_readout<<<ROWS/8, 128, 86400>>>(nodes, Wr);
    k_reduce<<<BB, 512>>>(out);
}

// round 4
// speedup vs baseline: 1.2008x; 1.2008x over previous
#include <cuda_runtime.h>

#define BB 32
#define NN 128
#define HH 100
#define ROWS (BB*NN)   // 4096

// Scratch (static device allocations — allowed)
__device__ float g_hidden[ROWS*HH];
__device__ float g_hv[ROWS*HH];
__device__ float g_hw[ROWS*HH];
__device__ float g_msg[ROWS*HH];
__device__ float g_gterm[ROWS*HH];
__device__ int   g_nodemask[ROWS];

// ---- packed f32x2 helpers (sm_100+; ptxas never auto-fuses these) ----------
__device__ __forceinline__ unsigned long long fma2(unsigned long long a,
                                                   unsigned long long b,
                                                   unsigned long long c) {
    unsigned long long d;
    asm("fma.rn.f32x2 %0, %1, %2, %3;" : "=l"(d) : "l"(a), "l"(b), "l"(c));
    return d;
}
__device__ __forceinline__ unsigned long long pack2(float w) {
    unsigned long long d;
    asm("mov.b64 %0, {%1, %1};" : "=l"(d) : "f"(w));
    return d;
}
__device__ __forceinline__ void unpack2(unsigned long long v, float& lo, float& hi) {
    asm("mov.b64 {%0, %1}, %2;" : "=f"(lo), "=f"(hi) : "l"(v));
}

// ---------------------------------------------------------------------------
// init: hidden = nodes; node_mask[row] = (sum_w sum_e edges[row,w,e]) != 0
// ---------------------------------------------------------------------------
__global__ void k_init(const float* __restrict__ nodes,
                       const float* __restrict__ edges) {
    int row = blockIdx.x;
    int tid = threadIdx.x;
    if (tid < HH) g_hidden[row*HH + tid] = nodes[row*HH + tid];

    const float4* e4 = (const float4*)edges + (size_t)row * NN;
    float4 e = e4[tid];
    float s = (e.x + e.y) + (e.z + e.w);
    __shared__ float red[128];
    red[tid] = s;
    __syncthreads();
    for (int off = 64; off > 0; off >>= 1) {
        if (tid < off) red[tid] += red[tid + off];
        __syncthreads();
    }
    if (tid == 0) g_nodemask[row] = (red[0] != 0.0f) ? 1 : 0;
}

// ---------------------------------------------------------------------------
// proj: hv = hidden @ Wv, hw = hidden @ Ww.
// grid=256, 256 threads, 16 rows/block. Wv+Ww in shared (80000B) + x-tile
// transposed (k, r0..r15) (6400B). Thread = (half = tid>>7, h = tid&127):
// each half computes 8 rows x 2 outputs via f32x2.
// ---------------------------------------------------------------------------
__global__ void __launch_bounds__(256)
k_proj(const float* __restrict__ Wv, const float* __restrict__ Ww) {
    extern __shared__ float smem[];
    float* sW = smem;           // [0,10000)=Wv, [10000,20000)=Ww
    float* sX = smem + 20000;   // 100*16 floats, layout sX[k*16 + r]

    int base = blockIdx.x * 16;
    int tid  = threadIdx.x;

    {
        const float4* wv4 = (const float4*)Wv;
        const float4* ww4 = (const float4*)Ww;
        float4* s4 = (float4*)sW;
        for (int i = tid; i < 2500; i += 256) {
            s4[i]        = wv4[i];
            s4[2500 + i] = ww4[i];
        }
    }
    for (int i = tid; i < 16*HH; i += 256) {
        int r = i / HH, k = i - r*HH;
        sX[k*16 + r] = g_hidden[(base + r)*HH + k];
    }
    __syncthreads();

    int h    = tid & 127;
    int half = tid >> 7;
    if (h < HH) {
        const ulonglong2* sX2 = (const ulonglong2*)sX;   // 4 per k
        unsigned long long av0=0, av1=0, av2=0, av3=0;
        unsigned long long aw0=0, aw1=0, aw2=0, aw3=0;
        #pragma unroll 2
        for (int k = 0; k < HH; k++) {
            ulonglong2 xa = sX2[k*4 + half*2];       // rows 0-3 of this half
            ulonglong2 xb = sX2[k*4 + half*2 + 1];   // rows 4-7
            unsigned long long wv = pack2(sW[k*HH + h]);
            unsigned long long ww = pack2(sW[10000 + k*HH + h]);
            av0 = fma2(xa.x, wv, av0); av1 = fma2(xa.y, wv, av1);
            av2 = fma2(xb.x, wv, av2); av3 = fma2(xb.y, wv, av3);
            aw0 = fma2(xa.x, ww, aw0); aw1 = fma2(xa.y, ww, aw1);
            aw2 = fma2(xb.x, ww, aw2); aw3 = fma2(xb.y, ww, aw3);
        }
        float rv[8], rw[8];
        unpack2(av0, rv[0], rv[1]); unpack2(av1, rv[2], rv[3]);
        unpack2(av2, rv[4], rv[5]); unpack2(av3, rv[6], rv[7]);
        unpack2(aw0, rw[0], rw[1]); unpack2(aw1, rw[2], rw[3]);
        unpack2(aw2, rw[4], rw[5]); unpack2(aw3, rw[6], rw[7]);
        int rbase = base + half*8;
        #pragma unroll
        for (int r = 0; r < 8; r++) {
            g_hv[(rbase + r)*HH + h] = rv[r];
            g_hw[(rbase + r)*HH + h] = rw[r];
        }
    }
}

// ---------------------------------------------------------------------------
// msg: messages[b,v,h] = sum_w [adj!=0] * relu(hv[v,h] + hw[w,h] + e.We)
// ---------------------------------------------------------------------------
__global__ void k_msg(const float* __restrict__ edges,
                      const float* __restrict__ We) {
    extern __shared__ float smem[];
    float*  s_hw  = smem;                        // 12800 floats
    float4* s_e   = (float4*)(smem + 12800);     // 512 float4
    float*  s_adj = smem + 12800 + 2048;         // 512 floats (0/1 mask)

    int bx  = blockIdx.x;
    int b   = bx >> 5;
    int v0  = (bx & 31) * 4;
    int tid = threadIdx.x;

    for (int i = tid; i < NN*HH; i += 512)
        s_hw[i] = g_hw[(b*NN)*HH + i];
    {
        int vloc = tid >> 7, w = tid & 127;
        const float4* e4 = (const float4*)edges;
        float4 e = e4[(size_t)((b*NN + v0 + vloc) * NN) + w];
        s_e[tid]   = e;
        float s = (e.x + e.y) + (e.z + e.w);
        s_adj[tid] = (s != 0.0f) ? 1.0f : 0.0f;
    }
    __syncthreads();

    int vloc = tid >> 7;
    int h    = tid & 127;
    if (h < HH) {
        float we0 = We[h], we1 = We[HH + h], we2 = We[2*HH + h], we3 = We[3*HH + h];
        float hvh = g_hv[(b*NN + v0 + vloc)*HH + h];
        const float4* ev = s_e   + (vloc << 7);
        const float*  av = s_adj + (vloc << 7);
        float acc0 = 0.f, acc1 = 0.f;
        #pragma unroll 4
        for (int w = 0; w < NN; w += 2) {
            float4 e0  = ev[w];
            float pre0 = hvh + s_hw[w*HH + h];
            pre0 = fmaf(e0.x, we0, pre0);
            pre0 = fmaf(e0.y, we1, pre0);
            pre0 = fmaf(e0.z, we2, pre0);
            pre0 = fmaf(e0.w, we3, pre0);
            acc0 = fmaf(fmaxf(pre0, 0.f), av[w], acc0);

            float4 e1  = ev[w + 1];
            float pre1 = hvh + s_hw[(w + 1)*HH + h];
            pre1 = fmaf(e1.x, we0, pre1);
            pre1 = fmaf(e1.y, we1, pre1);
            pre1 = fmaf(e1.z, we2, pre1);
            pre1 = fmaf(e1.w, we3, pre1);
            acc1 = fmaf(fmaxf(pre1, 0.f), av[w + 1], acc1);
        }
        g_msg[(b*NN + v0 + vloc)*HH + h] = acc0 + acc1;
    }
}

// ---------------------------------------------------------------------------
// update: hidden = node_mask ? tanh([hidden, msg] @ Wu) : hidden
// grid=256, 256 threads, 16 rows/block, Wu (80000B) + x-tile (12800B) shared.
// ---------------------------------------------------------------------------
__global__ void __launch_bounds__(256)
k_update(const float* __restrict__ Wu) {
    extern __shared__ float smem[];
    float* sW = smem;           // 20000 floats
    float* sX = smem + 20000;   // 200*16 floats

    int base = blockIdx.x * 16;
    int tid  = threadIdx.x;

    {
        const float4* w4 = (const float4*)Wu;
        float4* s4 = (float4*)sW;
        for (int i = tid; i < 5000; i += 256) s4[i] = w4[i];
    }
    for (int i = tid; i < 16*HH; i += 256) {
        int r = i / HH, k = i - r*HH;
        sX[k*16 + r]        = g_hidden[(base + r)*HH + k];
        sX[(HH + k)*16 + r] = g_msg   [(base + r)*HH + k];
    }
    __syncthreads();

    int h    = tid & 127;
    int half = tid >> 7;
    if (h < HH) {
        const ulonglong2* sX2 = (const ulonglong2*)sX;
        unsigned long long a0=0, a1=0, a2=0, a3=0;
        #pragma unroll 4
        for (int k = 0; k < 2*HH; k++) {
            ulonglong2 xa = sX2[k*4 + half*2];
            ulonglong2 xb = sX2[k*4 + half*2 + 1];
            unsigned long long w = pack2(sW[k*HH + h]);
            a0 = fma2(xa.x, w, a0); a1 = fma2(xa.y, w, a1);
            a2 = fma2(xb.x, w, a2); a3 = fma2(xb.y, w, a3);
        }
        float res[8];
        unpack2(a0, res[0], res[1]); unpack2(a1, res[2], res[3]);
        unpack2(a2, res[4], res[5]); unpack2(a3, res[6], res[7]);
        int rbase = base + half*8;
        #pragma unroll
        for (int r = 0; r < 8; r++) {
            float oldv = g_hidden[(rbase + r)*HH + h];
            g_hidden[(rbase + r)*HH + h] =
                g_nodemask[rbase + r] ? tanhf(res[r]) : oldv;
        }
    }
}

// ---------------------------------------------------------------------------
// readout terms: gterm = node_mask ? relu([hidden, nodes] @ Wr) : 0
// ---------------------------------------------------------------------------
__global__ void __launch_bounds__(256)
k_readout(const float* __restrict__ nodes, const float* __restrict__ Wr) {
    extern __shared__ float smem[];
    float* sW = smem;
    float* sX = smem + 20000;

    int base = blockIdx.x * 16;
    int tid  = threadIdx.x;

    {
        const float4* w4 = (const float4*)Wr;
        float4* s4 = (float4*)sW;
        for (int i = tid; i < 5000; i += 256) s4[i] = w4[i];
    }
    for (int i = tid; i < 16*HH; i += 256) {
        int r = i / HH, k = i - r*HH;
        sX[k*16 + r]        = g_hidden[(base + r)*HH + k];
        sX[(HH + k)*16 + r] = nodes   [(base + r)*HH + k];
    }
    __syncthreads();

    int h    = tid & 127;
    int half = tid >> 7;
    if (h < HH) {
        const ulonglong2* sX2 = (const ulonglong2*)sX;
        unsigned long long a0=0, a1=0, a2=0, a3=0;
        #pragma unroll 4
        for (int k = 0; k < 2*HH; k++) {
            ulonglong2 xa = sX2[k*4 + half*2];
            ulonglong2 xb = sX2[k*4 + half*2 + 1];
            unsigned long long w = pack2(sW[k*HH + h]);
            a0 = fma2(xa.x, w, a0); a1 = fma2(xa.y, w, a1);
            a2 = fma2(xb.x, w, a2); a3 = fma2(xb.y, w, a3);
        }
        float res[8];
        unpack2(a0, res[0], res[1]); unpack2(a1, res[2], res[3]);
        unpack2(a2, res[4], res[5]); unpack2(a3, res[6], res[7]);
        int rbase = base + half*8;
        #pragma unroll
        for (int r = 0; r < 8; r++) {
            float g = fmaxf(res[r], 0.f);
            g_gterm[(rbase + r)*HH + h] = g_nodemask[rbase + r] ? g : 0.f;
        }
    }
}

// ---------------------------------------------------------------------------
// reduce: out[b,h] = sum_v gterm[b,v,h]  (deterministic, no atomics)
// ---------------------------------------------------------------------------
__global__ void k_reduce(float* __restrict__ out) {
    int b   = blockIdx.x;
    int tid = threadIdx.x;           // 512
    int q   = tid >> 7;
    int h   = tid & 127;
    __shared__ float red[4][128];
    float acc = 0.f;
    if (h < HH) {
        int v0 = q * 32;
        #pragma unroll 4
        for (int v = v0; v < v0 + 32; v++)
            acc += g_gterm[(b*NN + v)*HH + h];
    }
    red[q][h] = acc;
    __syncthreads();
    if (q == 0 && h < HH)
        out[b*HH + h] = (red[0][h] + red[1][h]) + (red[2][h] + red[3][h]);
}

extern "C" void kernel_launch(void* const* d_in, const int* in_sizes, int n_in,
                              void* d_out, int out_size) {
    const float* nodes = (const float*)d_in[0];
    const float* edges = (const float*)d_in[1];
    const float* Wv    = (const float*)d_in[2];
    const float* Ww    = (const float*)d_in[3];
    const float* We    = (const float*)d_in[4];
    const float* Wu    = (const float*)d_in[5];
    const float* Wr    = (const float*)d_in[6];
    float* out = (float*)d_out;

    cudaFuncSetAttribute(k_msg,     cudaFuncAttributeMaxDynamicSharedMemorySize, 61440);
    cudaFuncSetAttribute(k_proj,    cudaFuncAttributeMaxDynamicSharedMemorySize, 86400);
    cudaFuncSetAttribute(k_update,  cudaFuncAttributeMaxDynamicSharedMemorySize, 92800);
    cudaFuncSetAttribute(k_readout, cudaFuncAttributeMaxDynamicSharedMemorySize, 92800);

    k_init<<<ROWS, 128>>>(nodes, edges);
    for (int p = 0; p < 3; p++) {
        k_proj<<<ROWS/16, 256, 86400>>>(Wv, Ww);
        k_msg<<<1024, 512, 61440>>>(edges, We);
        k_update<<<ROWS/16, 256, 92800>>>(Wu);
    }
    k_readout<<<ROWS/16, 256, 92800>>>(nodes, Wr);
    k_reduce<<<BB, 512>>>(out);
}